// round 9
// baseline (speedup 1.0000x reference)
#include <cuda_runtime.h>
#include <cuda_fp16.h>
#include <cstdint>

// ---------------------------------------------------------------------------
// SimpleMaxViTBlock: LN1 -> per-token head-mixing attention -> +res
//                    -> LN2 -> FFN -> +res
// GEMMs: mma.sync m16n8k16 fp16 with fp16 accumulators, promoted to fp32
// every BK=32 chunk. ldmatrix fragments, 4 warps (2x2), 64x64 warp tiles.
// ---------------------------------------------------------------------------

constexpr int TOKENS = 65536;
constexpr int DIM    = 256;
constexpr int HEADS  = 8;
constexpr int HD     = 32;
constexpr int FFNDIM = 1024;

// Scratch (device globals: allocation-free rule)
__device__ __half g_xn  [ (size_t)TOKENS * DIM    ];
__device__ __half g_qkv [ (size_t)TOKENS * 3*DIM  ];
__device__ __half g_attn[ (size_t)TOKENS * DIM    ];
__device__ float  g_y   [ (size_t)TOKENS * DIM    ];
__device__ __half g_h   [ (size_t)TOKENS * FFNDIM ];
__device__ __half g_w   [ 786432 ];   // fp16-rounded weights

constexpr int W_QKV  = 0;
constexpr int W_PROJ = 196608;
constexpr int W_FFN1 = 262144;
constexpr int W_FFN2 = 524288;

// ===================== helpers ==============================================
__device__ __forceinline__ uint32_t smem_u32(const void* p) {
    uint32_t a;
    asm("{ .reg .u64 t; cvta.to.shared.u64 t, %1; cvt.u32.u64 %0, t; }"
        : "=r"(a) : "l"(p));
    return a;
}
__device__ __forceinline__ void cp_async16(uint32_t saddr, const void* gaddr) {
    asm volatile("cp.async.cg.shared.global [%0], [%1], 16;"
                 :: "r"(saddr), "l"(gaddr) : "memory");
}
__device__ __forceinline__ void cp_commit() {
    asm volatile("cp.async.commit_group;" ::: "memory");
}
template<int N>
__device__ __forceinline__ void cp_wait() {
    asm volatile("cp.async.wait_group %0;" :: "n"(N) : "memory");
}
__device__ __forceinline__ void ldm_x4(uint32_t& r0, uint32_t& r1,
                                       uint32_t& r2, uint32_t& r3, uint32_t addr) {
    asm volatile("ldmatrix.sync.aligned.m8n8.x4.shared.b16 {%0,%1,%2,%3}, [%4];"
                 : "=r"(r0), "=r"(r1), "=r"(r2), "=r"(r3) : "r"(addr));
}
// fp16-accumulator MMA: d/c are 2 b32 regs holding 4 halves (c0..c3)
__device__ __forceinline__ void mma_f16acc(
    uint32_t& d0, uint32_t& d1,
    uint32_t a0, uint32_t a1, uint32_t a2, uint32_t a3,
    uint32_t b0, uint32_t b1)
{
    asm volatile(
        "mma.sync.aligned.m16n8k16.row.col.f16.f16.f16.f16 "
        "{%0,%1}, {%2,%3,%4,%5}, {%6,%7}, {%0,%1};"
        : "+r"(d0), "+r"(d1)
        : "r"(a0), "r"(a1), "r"(a2), "r"(a3), "r"(b0), "r"(b1));
}

// ===================== fp16 mma.sync GEMM ===================================
// C[m,n] = epi( sum_k A[m,k]*B[n,k] + bias[n] [+res] )
// A:[M,K], B:[N,K] row-major __half. CTA 128x128, BK=32 halves,
// double-buffered cp.async, 4 warps (2x2), warp tile 64x64, ldmatrix frags.
// fp16 accum within a chunk, promoted to fp32 each chunk.
// MODE: 0 = bias -> half out, 1 = bias+relu -> half out, 2 = bias+res -> f32
constexpr int TILE  = 128;
constexpr int BK    = 32;
constexpr int LDU   = 20;              // u32 per smem row (= 40 halves, 80B)
constexpr int SLABU = TILE * LDU;      // 2560 u32 per stage per matrix

template<int MODE, typename OutT>
__global__ void __launch_bounds__(128, 2) mma_gemm(
    const __half* __restrict__ A, const __half* __restrict__ B,
    const float* __restrict__ bias, const float* __restrict__ res,
    OutT* __restrict__ C, int K, int N)
{
    __shared__ __align__(16) uint32_t sm[4 * SLABU];   // 40960 B
    uint32_t* As = sm;                  // [2][128][20]
    uint32_t* Bs = sm + 2 * SLABU;
    const uint32_t As_u = smem_u32(As);
    const uint32_t Bs_u = smem_u32(Bs);

    const int tid  = threadIdx.x;
    const int wid  = tid >> 5;
    const int lane = tid & 31;
    const int gid  = lane >> 2;     // 0..7
    const int tg   = lane & 3;      // 0..3

    const int bm = blockIdx.y * TILE;
    const int bn = blockIdx.x * TILE;
    const int m_off = (wid >> 1) * 64;   // 0 or 64
    const int n_off = (wid & 1) * 64;    // 0 or 64

    // ldmatrix per-lane address components
    const int lrow8 = lane & 7;
    const int a_row = (lrow8 + ((lane >> 3) & 1) * 8);
    const int a_kof = (lane >> 4) * 4;
    const int b_row = (lrow8 + ((lane >> 4) & 1) * 8);
    const int b_kof = ((lane >> 3) & 1) * 4;

    // cp.async mapping: 512 16B-transfers per matrix, 128 threads x 4 iters
    const int crow = tid >> 2;          // +32 per it
    const int cc4  = (tid & 3) * 4;     // u32 offset within 16 u32 of row data

    float d[4][8][4];
#pragma unroll
    for (int mt = 0; mt < 4; mt++)
#pragma unroll
        for (int nt = 0; nt < 8; nt++)
#pragma unroll
            for (int j = 0; j < 4; j++) d[mt][nt][j] = 0.0f;

    const int C_CHUNKS = K / BK;

    // stage 0
    {
#pragma unroll
        for (int it = 0; it < 4; it++) {
            int row = crow + it * 32;
            cp_async16(As_u + (uint32_t)(row * LDU + cc4) * 4,
                       A + (size_t)(bm + row) * K + cc4 * 2);
            cp_async16(Bs_u + (uint32_t)(row * LDU + cc4) * 4,
                       B + (size_t)(bn + row) * K + cc4 * 2);
        }
        cp_commit();
    }

    for (int c = 0; c < C_CHUNKS; c++) {
        const int buf = c & 1;
        if (c + 1 < C_CHUNKS) {
            const int nb  = (c + 1) & 1;
            const int k0g = (c + 1) * BK;
#pragma unroll
            for (int it = 0; it < 4; it++) {
                int row = crow + it * 32;
                cp_async16(As_u + (uint32_t)((nb * SLABU + row * LDU + cc4) * 4),
                           A + (size_t)(bm + row) * K + k0g + cc4 * 2);
                cp_async16(Bs_u + (uint32_t)((nb * SLABU + row * LDU + cc4) * 4),
                           B + (size_t)(bn + row) * K + k0g + cc4 * 2);
            }
            cp_commit();
            cp_wait<1>();
        } else {
            cp_wait<0>();
        }
        __syncthreads();

        const uint32_t Ab = As_u + (uint32_t)(buf * SLABU) * 4;
        const uint32_t Bb = Bs_u + (uint32_t)(buf * SLABU) * 4;

        // fp16 chunk accumulators (zeroed each chunk)
        uint32_t dh[4][8][2];
#pragma unroll
        for (int mt = 0; mt < 4; mt++)
#pragma unroll
            for (int nt = 0; nt < 8; nt++) { dh[mt][nt][0] = 0u; dh[mt][nt][1] = 0u; }

#pragma unroll
        for (int ks = 0; ks < 2; ks++) {
            const int ko = ks * 8;      // u32 offset (16 halves per k-step)

            uint32_t a[4][4];
#pragma unroll
            for (int mt = 0; mt < 4; mt++) {
                uint32_t addr = Ab + (uint32_t)(
                    (m_off + mt * 16 + a_row) * LDU + ko + a_kof) * 4;
                ldm_x4(a[mt][0], a[mt][1], a[mt][2], a[mt][3], addr);
            }
            uint32_t b[8][2];
#pragma unroll
            for (int np = 0; np < 4; np++) {
                uint32_t addr = Bb + (uint32_t)(
                    (n_off + np * 16 + b_row) * LDU + ko + b_kof) * 4;
                ldm_x4(b[2*np][0], b[2*np][1], b[2*np+1][0], b[2*np+1][1], addr);
            }
#pragma unroll
            for (int mt = 0; mt < 4; mt++)
#pragma unroll
                for (int nt = 0; nt < 8; nt++)
                    mma_f16acc(dh[mt][nt][0], dh[mt][nt][1],
                               a[mt][0], a[mt][1], a[mt][2], a[mt][3],
                               b[nt][0], b[nt][1]);
        }

        // promote chunk fp16 partials into fp32 master accumulators
#pragma unroll
        for (int mt = 0; mt < 4; mt++)
#pragma unroll
            for (int nt = 0; nt < 8; nt++) {
                float2 lo = __half22float2(*(__half2*)&dh[mt][nt][0]);
                float2 hi = __half22float2(*(__half2*)&dh[mt][nt][1]);
                d[mt][nt][0] += lo.x; d[mt][nt][1] += lo.y;
                d[mt][nt][2] += hi.x; d[mt][nt][3] += hi.y;
            }
        __syncthreads();
    }

    // ---- epilogue ----
#pragma unroll
    for (int nt = 0; nt < 8; nt++) {
        const int n = bn + n_off + nt * 8 + 2 * tg;
        const float2 bv = *(const float2*)&bias[n];
#pragma unroll
        for (int mt = 0; mt < 4; mt++) {
            const int m0 = bm + m_off + mt * 16 + gid;
#pragma unroll
            for (int half_i = 0; half_i < 2; half_i++) {
                const int m = m0 + half_i * 8;
                float vx = d[mt][nt][half_i * 2 + 0] + bv.x;
                float vy = d[mt][nt][half_i * 2 + 1] + bv.y;
                if (MODE == 1) { vx = fmaxf(vx, 0.f); vy = fmaxf(vy, 0.f); }
                if (MODE == 2) {
                    const float2 r = *(const float2*)&res[(size_t)m * N + n];
                    float2 v; v.x = vx + r.x; v.y = vy + r.y;
                    *(float2*)&((float*)C)[(size_t)m * N + n] = v;
                } else {
                    *(__half2*)&((__half*)C)[(size_t)m * N + n] =
                        __floats2half2_rn(vx, vy);
                }
            }
        }
    }
}

// ===================== weight rounding (all four, one launch) ===============
__global__ void __launch_bounds__(256) round_w_all(
    const float* __restrict__ qkv_w, const float* __restrict__ proj_w,
    const float* __restrict__ ffn_w1, const float* __restrict__ ffn_w2,
    __half* __restrict__ dst)
{
    int i = blockIdx.x * 256 + threadIdx.x;          // float4 index, 196608 total
    const float* src;
    int local;
    if (i < 49152)       { src = qkv_w;  local = i;           }
    else if (i < 65536)  { src = proj_w; local = i - 49152;   }
    else if (i < 131072) { src = ffn_w1; local = i - 65536;   }
    else                 { src = ffn_w2; local = i - 131072;  }
    float4 v = ((const float4*)src)[local];
    __half2 lo = __floats2half2_rn(v.x, v.y);
    __half2 hi = __floats2half2_rn(v.z, v.w);
    uint2 o; o.x = *(uint32_t*)&lo; o.y = *(uint32_t*)&hi;
    ((uint2*)dst)[i] = o;
}

// ===================== LayerNorm (one warp per 256-float row) ===============
__global__ void __launch_bounds__(256) ln_kernel(
    const float* __restrict__ x, const float* __restrict__ g,
    const float* __restrict__ b, __half* __restrict__ out)
{
    int row  = (blockIdx.x * blockDim.x + threadIdx.x) >> 5;
    int lane = threadIdx.x & 31;
    const float4* xr = (const float4*)(x + (size_t)row * DIM);
    float4 v0 = xr[lane];
    float4 v1 = xr[lane + 32];

    float s = v0.x + v0.y + v0.z + v0.w + v1.x + v1.y + v1.z + v1.w;
    float q = v0.x*v0.x + v0.y*v0.y + v0.z*v0.z + v0.w*v0.w
            + v1.x*v1.x + v1.y*v1.y + v1.z*v1.z + v1.w*v1.w;
#pragma unroll
    for (int o = 16; o > 0; o >>= 1) {
        s += __shfl_xor_sync(0xffffffffu, s, o);
        q += __shfl_xor_sync(0xffffffffu, q, o);
    }
    float mean = s * (1.0f / 256.0f);
    float var  = q * (1.0f / 256.0f) - mean * mean;
    float inv  = rsqrtf(var + 1e-5f);

    const float4* g4 = (const float4*)g;
    const float4* b4 = (const float4*)b;
    float4 ga = g4[lane], gb = g4[lane + 32];
    float4 ba = b4[lane], bb = b4[lane + 32];

    __half2 h0 = __floats2half2_rn((v0.x - mean) * inv * ga.x + ba.x,
                                   (v0.y - mean) * inv * ga.y + ba.y);
    __half2 h1 = __floats2half2_rn((v0.z - mean) * inv * ga.z + ba.z,
                                   (v0.w - mean) * inv * ga.w + ba.w);
    __half2 h2 = __floats2half2_rn((v1.x - mean) * inv * gb.x + bb.x,
                                   (v1.y - mean) * inv * gb.y + bb.y);
    __half2 h3 = __floats2half2_rn((v1.z - mean) * inv * gb.z + bb.z,
                                   (v1.w - mean) * inv * gb.w + bb.w);

    __half* orow = out + (size_t)row * DIM;
    uint2 p0; p0.x = *(uint32_t*)&h0; p0.y = *(uint32_t*)&h1;
    uint2 p1; p1.x = *(uint32_t*)&h2; p1.y = *(uint32_t*)&h3;
    *(uint2*)(orow + lane * 4)       = p0;
    *(uint2*)(orow + 128 + lane * 4) = p1;
}

// ===================== Per-token head-mixing attention ======================
__global__ void __launch_bounds__(128) attn_kernel(
    const __half* __restrict__ qkv, __half* __restrict__ out)
{
    __shared__ __align__(16) float ks[16][HEADS][HD + 1];
    __shared__ __align__(16) float vs[16][HEADS][HD + 1];

    const int tok0 = blockIdx.x * 16;
    const int tid  = threadIdx.x;

#pragma unroll
    for (int it = 0; it < 4; it++) {
        int fi = tid + it * 128;            // 0..511
        int t  = fi >> 5;
        int c  = fi & 31;
        int g  = c >> 2;
        int d  = (c & 3) * 8;
        const __half* base = qkv + (size_t)(tok0 + t) * 768;
        uint4 kv = *(const uint4*)(base + 256 + g * HD + d);
        uint4 vv = *(const uint4*)(base + 512 + g * HD + d);
        const __half2* kh = (const __half2*)&kv;
        const __half2* vh = (const __half2*)&vv;
#pragma unroll
        for (int j = 0; j < 4; j++) {
            float2 kf = __half22float2(kh[j]);
            float2 vf = __half22float2(vh[j]);
            ks[t][g][d + 2*j]     = kf.x;
            ks[t][g][d + 2*j + 1] = kf.y;
            vs[t][g][d + 2*j]     = vf.x;
            vs[t][g][d + 2*j + 1] = vf.y;
        }
    }
    __syncthreads();

    const int t = tid >> 3;
    const int h = tid & 7;
    const size_t row = (size_t)(tok0 + t);

    float q[HD];
    {
        const __half* qrow = qkv + row * 768 + h * HD;
#pragma unroll
        for (int c = 0; c < 4; c++) {
            uint4 qv = *(const uint4*)(qrow + c * 8);
            const __half2* qh = (const __half2*)&qv;
#pragma unroll
            for (int j = 0; j < 4; j++) {
                float2 qf = __half22float2(qh[j]);
                q[c * 8 + 2*j]     = qf.x;
                q[c * 8 + 2*j + 1] = qf.y;
            }
        }
    }

    const float scale = 0.17677669529663688f;   // 1/sqrt(32)
    float sc[HEADS];
    float mx = -1e30f;
#pragma unroll
    for (int g = 0; g < HEADS; g++) {
        float s = 0.0f;
#pragma unroll
        for (int d = 0; d < HD; d++) s += q[d] * ks[t][g][d];
        s *= scale;
        sc[g] = s;
        mx = fmaxf(mx, s);
    }
    float sum = 0.0f;
#pragma unroll
    for (int g = 0; g < HEADS; g++) {
        float e = __expf(sc[g] - mx);
        sc[g] = e;
        sum += e;
    }
    const float inv = 1.0f / sum;

    float acc[HD];
#pragma unroll
    for (int d = 0; d < HD; d++) acc[d] = 0.0f;
#pragma unroll
    for (int g = 0; g < HEADS; g++) {
        const float p = sc[g];
#pragma unroll
        for (int d = 0; d < HD; d++) acc[d] += p * vs[t][g][d];
    }

    __half* orow = out + row * DIM + h * HD;
#pragma unroll
    for (int c = 0; c < 4; c++) {
        __half2 o0 = __floats2half2_rn(acc[c*8+0] * inv, acc[c*8+1] * inv);
        __half2 o1 = __floats2half2_rn(acc[c*8+2] * inv, acc[c*8+3] * inv);
        __half2 o2 = __floats2half2_rn(acc[c*8+4] * inv, acc[c*8+5] * inv);
        __half2 o3 = __floats2half2_rn(acc[c*8+6] * inv, acc[c*8+7] * inv);
        uint4 p;
        p.x = *(uint32_t*)&o0; p.y = *(uint32_t*)&o1;
        p.z = *(uint32_t*)&o2; p.w = *(uint32_t*)&o3;
        *(uint4*)(orow + c * 8) = p;
    }
}

// ===================== Launch ===============================================
extern "C" void kernel_launch(void* const* d_in, const int* in_sizes, int n_in,
                              void* d_out, int out_size)
{
    const float* x      = (const float*)d_in[0];
    const float* ln1_g  = (const float*)d_in[1];
    const float* ln1_b  = (const float*)d_in[2];
    const float* qkv_w  = (const float*)d_in[3];
    const float* qkv_b  = (const float*)d_in[4];
    const float* proj_w = (const float*)d_in[5];
    const float* proj_b = (const float*)d_in[6];
    const float* ln2_g  = (const float*)d_in[7];
    const float* ln2_b  = (const float*)d_in[8];
    const float* ffn_w1 = (const float*)d_in[9];
    const float* ffn_b1 = (const float*)d_in[10];
    const float* ffn_w2 = (const float*)d_in[11];
    const float* ffn_b2 = (const float*)d_in[12];

    __half *xn, *qkv, *attn, *h, *w;
    float  *y;
    cudaGetSymbolAddress((void**)&xn,   g_xn);
    cudaGetSymbolAddress((void**)&qkv,  g_qkv);
    cudaGetSymbolAddress((void**)&attn, g_attn);
    cudaGetSymbolAddress((void**)&y,    g_y);
    cudaGetSymbolAddress((void**)&h,    g_h);
    cudaGetSymbolAddress((void**)&w,    g_w);
    float* out = (float*)d_out;

    const int MROWS = TOKENS / TILE;   // 512

    // 0) round all weights to fp16 in one launch (196608 float4s)
    round_w_all<<<196608 / 256, 256>>>(qkv_w, proj_w, ffn_w1, ffn_w2, w);

    // 1) LN1 (half out)
    ln_kernel<<<TOKENS / 8, 256>>>(x, ln1_g, ln1_b, xn);
    // 2) QKV = xn @ qkv_w^T + qkv_b          [65536, 768] half
    mma_gemm<0, __half><<<dim3(768 / TILE, MROWS), 128>>>(
        xn, w + W_QKV, qkv_b, nullptr, qkv, DIM, 3 * DIM);
    // 3) per-token head-mixing attention (half out)
    attn_kernel<<<TOKENS / 16, 128>>>(qkv, attn);
    // 4) y = x + attn @ proj_w^T + proj_b    [65536, 256] f32
    mma_gemm<2, float><<<dim3(DIM / TILE, MROWS), 128>>>(
        attn, w + W_PROJ, proj_b, x, y, DIM, DIM);
    // 5) LN2 (half out)
    ln_kernel<<<TOKENS / 8, 256>>>(y, ln2_g, ln2_b, xn);
    // 6) h = relu(xn @ ffn_w1^T + ffn_b1)    [65536, 1024] half
    mma_gemm<1, __half><<<dim3(FFNDIM / TILE, MROWS), 128>>>(
        xn, w + W_FFN1, ffn_b1, nullptr, h, DIM, FFNDIM);
    // 7) out = y + h @ ffn_w2^T + ffn_b2     [65536, 256] f32
    mma_gemm<2, float><<<dim3(DIM / TILE, MROWS), 128>>>(
        h, w + W_FFN2, ffn_b2, y, out, FFNDIM, DIM);
}

// round 10
// speedup vs baseline: 1.1781x; 1.1781x over previous
#include <cuda_runtime.h>
#include <cuda_fp16.h>
#include <cstdint>

// ---------------------------------------------------------------------------
// SimpleMaxViTBlock: LN1 -> [attention + proj + LN2 fused] -> FFN -> +res
// GEMMs: mma.sync m16n8k16 fp16, fp32 accum (R8 datapath — measured at the
// 512 MAC/cyc/SM legacy-HMMA floor). This round fuses the per-token head-mix
// attention, the proj GEMM and LN2 into one kernel (CTA = 128 rows x N=256).
// ---------------------------------------------------------------------------

constexpr int TOKENS = 65536;
constexpr int DIM    = 256;
constexpr int HEADS  = 8;
constexpr int HD     = 32;
constexpr int FFNDIM = 1024;

// Scratch (device globals: allocation-free rule)
__device__ __half g_xn  [ (size_t)TOKENS * DIM    ];
__device__ __half g_qkv [ (size_t)TOKENS * 3*DIM  ];
__device__ float  g_y   [ (size_t)TOKENS * DIM    ];
__device__ __half g_h   [ (size_t)TOKENS * FFNDIM ];
__device__ __half g_w   [ 786432 ];   // fp16-rounded weights

constexpr int W_QKV  = 0;
constexpr int W_PROJ = 196608;
constexpr int W_FFN1 = 262144;
constexpr int W_FFN2 = 524288;

// ===================== helpers ==============================================
__device__ __forceinline__ uint32_t smem_u32(const void* p) {
    uint32_t a;
    asm("{ .reg .u64 t; cvta.to.shared.u64 t, %1; cvt.u32.u64 %0, t; }"
        : "=r"(a) : "l"(p));
    return a;
}
__device__ __forceinline__ void cp_async16(uint32_t saddr, const void* gaddr) {
    asm volatile("cp.async.cg.shared.global [%0], [%1], 16;"
                 :: "r"(saddr), "l"(gaddr) : "memory");
}
__device__ __forceinline__ void cp_commit() {
    asm volatile("cp.async.commit_group;" ::: "memory");
}
template<int N>
__device__ __forceinline__ void cp_wait() {
    asm volatile("cp.async.wait_group %0;" :: "n"(N) : "memory");
}
__device__ __forceinline__ void ldm_x4(uint32_t& r0, uint32_t& r1,
                                       uint32_t& r2, uint32_t& r3, uint32_t addr) {
    asm volatile("ldmatrix.sync.aligned.m8n8.x4.shared.b16 {%0,%1,%2,%3}, [%4];"
                 : "=r"(r0), "=r"(r1), "=r"(r2), "=r"(r3) : "r"(addr));
}
__device__ __forceinline__ void mma_f16(
    float& d0, float& d1, float& d2, float& d3,
    uint32_t a0, uint32_t a1, uint32_t a2, uint32_t a3,
    uint32_t b0, uint32_t b1)
{
    asm volatile(
        "mma.sync.aligned.m16n8k16.row.col.f32.f16.f16.f32 "
        "{%0,%1,%2,%3}, {%4,%5,%6,%7}, {%8,%9}, {%0,%1,%2,%3};"
        : "+f"(d0), "+f"(d1), "+f"(d2), "+f"(d3)
        : "r"(a0), "r"(a1), "r"(a2), "r"(a3), "r"(b0), "r"(b1));
}

// ===================== fp16 mma.sync GEMM (R8 datapath) =====================
// C[m,n] = epi( sum_k A[m,k]*B[n,k] + bias[n] [+res] )
// CTA 128x128, BK=32 halves, double-buffered cp.async, 4 warps (2x2),
// warp tile 64x64, ldmatrix fragments, fp32 accumulators, 2 CTAs/SM.
// MODE: 0 = bias -> half out, 1 = bias+relu -> half out, 2 = bias+res -> f32
constexpr int TILE  = 128;
constexpr int BK    = 32;
constexpr int LDU   = 20;              // u32 per smem row (= 40 halves, 80B)
constexpr int SLABU = TILE * LDU;      // 2560 u32 per stage per matrix

template<int MODE, typename OutT>
__global__ void __launch_bounds__(128, 2) mma_gemm(
    const __half* __restrict__ A, const __half* __restrict__ B,
    const float* __restrict__ bias, const float* __restrict__ res,
    OutT* __restrict__ C, int K, int N)
{
    __shared__ __align__(16) uint32_t sm[4 * SLABU];   // 40960 B
    uint32_t* As = sm;
    uint32_t* Bs = sm + 2 * SLABU;
    const uint32_t As_u = smem_u32(As);
    const uint32_t Bs_u = smem_u32(Bs);

    const int tid  = threadIdx.x;
    const int wid  = tid >> 5;
    const int lane = tid & 31;
    const int gid  = lane >> 2;
    const int tg   = lane & 3;

    const int bm = blockIdx.y * TILE;
    const int bn = blockIdx.x * TILE;
    const int m_off = (wid >> 1) * 64;
    const int n_off = (wid & 1) * 64;

    const int lrow8 = lane & 7;
    const int a_row = (lrow8 + ((lane >> 3) & 1) * 8);
    const int a_kof = (lane >> 4) * 4;
    const int b_row = (lrow8 + ((lane >> 4) & 1) * 8);
    const int b_kof = ((lane >> 3) & 1) * 4;

    const int crow = tid >> 2;
    const int cc4  = (tid & 3) * 4;

    float d[4][8][4];
#pragma unroll
    for (int mt = 0; mt < 4; mt++)
#pragma unroll
        for (int nt = 0; nt < 8; nt++)
#pragma unroll
            for (int j = 0; j < 4; j++) d[mt][nt][j] = 0.0f;

    const int C_CHUNKS = K / BK;

    {
#pragma unroll
        for (int it = 0; it < 4; it++) {
            int row = crow + it * 32;
            cp_async16(As_u + (uint32_t)(row * LDU + cc4) * 4,
                       A + (size_t)(bm + row) * K + cc4 * 2);
            cp_async16(Bs_u + (uint32_t)(row * LDU + cc4) * 4,
                       B + (size_t)(bn + row) * K + cc4 * 2);
        }
        cp_commit();
    }

    for (int c = 0; c < C_CHUNKS; c++) {
        const int buf = c & 1;
        if (c + 1 < C_CHUNKS) {
            const int nb  = (c + 1) & 1;
            const int k0g = (c + 1) * BK;
#pragma unroll
            for (int it = 0; it < 4; it++) {
                int row = crow + it * 32;
                cp_async16(As_u + (uint32_t)((nb * SLABU + row * LDU + cc4) * 4),
                           A + (size_t)(bm + row) * K + k0g + cc4 * 2);
                cp_async16(Bs_u + (uint32_t)((nb * SLABU + row * LDU + cc4) * 4),
                           B + (size_t)(bn + row) * K + k0g + cc4 * 2);
            }
            cp_commit();
            cp_wait<1>();
        } else {
            cp_wait<0>();
        }
        __syncthreads();

        const uint32_t Ab = As_u + (uint32_t)(buf * SLABU) * 4;
        const uint32_t Bb = Bs_u + (uint32_t)(buf * SLABU) * 4;

#pragma unroll
        for (int ks = 0; ks < 2; ks++) {
            const int ko = ks * 8;
            uint32_t a[4][4];
#pragma unroll
            for (int mt = 0; mt < 4; mt++) {
                uint32_t addr = Ab + (uint32_t)(
                    (m_off + mt * 16 + a_row) * LDU + ko + a_kof) * 4;
                ldm_x4(a[mt][0], a[mt][1], a[mt][2], a[mt][3], addr);
            }
            uint32_t b[8][2];
#pragma unroll
            for (int np = 0; np < 4; np++) {
                uint32_t addr = Bb + (uint32_t)(
                    (n_off + np * 16 + b_row) * LDU + ko + b_kof) * 4;
                ldm_x4(b[2*np][0], b[2*np][1], b[2*np+1][0], b[2*np+1][1], addr);
            }
#pragma unroll
            for (int mt = 0; mt < 4; mt++)
#pragma unroll
                for (int nt = 0; nt < 8; nt++)
                    mma_f16(d[mt][nt][0], d[mt][nt][1], d[mt][nt][2], d[mt][nt][3],
                            a[mt][0], a[mt][1], a[mt][2], a[mt][3],
                            b[nt][0], b[nt][1]);
        }
        __syncthreads();
    }

#pragma unroll
    for (int nt = 0; nt < 8; nt++) {
        const int n = bn + n_off + nt * 8 + 2 * tg;
        const float2 bv = *(const float2*)&bias[n];
#pragma unroll
        for (int mt = 0; mt < 4; mt++) {
            const int m0 = bm + m_off + mt * 16 + gid;
#pragma unroll
            for (int half_i = 0; half_i < 2; half_i++) {
                const int m = m0 + half_i * 8;
                float vx = d[mt][nt][half_i * 2 + 0] + bv.x;
                float vy = d[mt][nt][half_i * 2 + 1] + bv.y;
                if (MODE == 1) { vx = fmaxf(vx, 0.f); vy = fmaxf(vy, 0.f); }
                if (MODE == 2) {
                    const float2 r = *(const float2*)&res[(size_t)m * N + n];
                    float2 v; v.x = vx + r.x; v.y = vy + r.y;
                    *(float2*)&((float*)C)[(size_t)m * N + n] = v;
                } else {
                    *(__half2*)&((__half*)C)[(size_t)m * N + n] =
                        __floats2half2_rn(vx, vy);
                }
            }
        }
    }
}

// ===================== fused attention + proj GEMM + LN2 ====================
// Per CTA: 128 tokens, full N=256.
// Prologue: per-token 8x8 head-mix attention from g_qkv -> resident A smem.
// Mainloop: A resident (K=256), B (proj_w) double-buffered, HMMA.
// Epilogue: y = x + A@B^T + bias (write f32); LN2 over each row -> xn (half).
constexpr int LDA_U  = 132;             // u32 per As row (264 halves, 528B)
constexpr int PBS_U  = 256 * LDU;       // 5120 u32 per B stage
constexpr int FUSED_SMEM = (128 * LDA_U + 2 * PBS_U) * 4 + 128 * 4 * 8; // 112640

__global__ void __launch_bounds__(256, 1) fused_attn_proj_ln(
    const __half* __restrict__ qkv, const __half* __restrict__ Bw,
    const float* __restrict__ bias, const float* __restrict__ x,
    const float* __restrict__ ln2g, const float* __restrict__ ln2b,
    float* __restrict__ y, __half* __restrict__ xn)
{
    extern __shared__ uint32_t smx[];
    uint32_t* As = smx;                          // [128][132]
    uint32_t* Bs = smx + 128 * LDA_U;            // [2][256][20]
    float2*   red = (float2*)(smx + 128 * LDA_U + 2 * PBS_U);  // [128][4]
    const uint32_t As_u = smem_u32(As);
    const uint32_t Bs_u = smem_u32(Bs);

    const int tid  = threadIdx.x;
    const int wid  = tid >> 5;
    const int lane = tid & 31;
    const int gid  = lane >> 2;
    const int tg   = lane & 3;

    const int bm = blockIdx.x * 128;
    const int m_off = (wid >> 2) * 64;   // 0 or 64
    const int n_off = (wid & 3) * 64;    // 0,64,128,192
    const int wn    = wid & 3;

    const int lrow8 = lane & 7;
    const int a_row = (lrow8 + ((lane >> 3) & 1) * 8);
    const int a_kof = (lane >> 4) * 4;
    const int b_row = (lrow8 + ((lane >> 4) & 1) * 8);
    const int b_kof = ((lane >> 3) & 1) * 4;

    // B cp.async mapping: 256 rows x 4 uint4 per 32-half chunk; 256 thr x 4 it
    const int brow = tid >> 2;           // +64 per it... (tid>>2 in 0..63)
    const int bc4  = (tid & 3) * 4;      // u32 offset

    // ---- issue B chunk 0, then do attention prologue (overlap) ----
    {
#pragma unroll
        for (int it = 0; it < 4; it++) {
            int row = brow + it * 64;
            cp_async16(Bs_u + (uint32_t)(row * LDU + bc4) * 4,
                       Bw + (size_t)row * DIM + bc4 * 2);
        }
        cp_commit();
    }

    // ---- attention prologue: 1024 (token,head) items, 4 per thread ----
#pragma unroll
    for (int it = 0; it < 4; it++) {
        const int item = tid + it * 256;
        const int t = item >> 3;
        const int h = item & 7;
        const __half* base = qkv + (size_t)(bm + t) * 768;

        float q[HD];
#pragma unroll
        for (int c4 = 0; c4 < 4; c4++) {
            uint4 qv = *(const uint4*)(base + h * HD + c4 * 8);
            const __half2* qh = (const __half2*)&qv;
#pragma unroll
            for (int j = 0; j < 4; j++) {
                float2 f = __half22float2(qh[j]);
                q[c4 * 8 + 2*j] = f.x; q[c4 * 8 + 2*j + 1] = f.y;
            }
        }

        const float scale = 0.17677669529663688f;   // 1/sqrt(32)
        float sc[HEADS];
        float mx = -1e30f;
#pragma unroll
        for (int g = 0; g < HEADS; g++) {
            float s = 0.0f;
#pragma unroll
            for (int c4 = 0; c4 < 4; c4++) {
                uint4 kv = *(const uint4*)(base + 256 + g * HD + c4 * 8);
                const __half2* kh = (const __half2*)&kv;
#pragma unroll
                for (int j = 0; j < 4; j++) {
                    float2 f = __half22float2(kh[j]);
                    s += q[c4 * 8 + 2*j] * f.x + q[c4 * 8 + 2*j + 1] * f.y;
                }
            }
            s *= scale;
            sc[g] = s;
            mx = fmaxf(mx, s);
        }
        float sum = 0.0f;
#pragma unroll
        for (int g = 0; g < HEADS; g++) {
            float e = __expf(sc[g] - mx);
            sc[g] = e;
            sum += e;
        }
        const float inv = 1.0f / sum;

        float acc[HD];
#pragma unroll
        for (int d0 = 0; d0 < HD; d0++) acc[d0] = 0.0f;
#pragma unroll
        for (int g = 0; g < HEADS; g++) {
            const float p = sc[g];
#pragma unroll
            for (int c4 = 0; c4 < 4; c4++) {
                uint4 vv = *(const uint4*)(base + 512 + g * HD + c4 * 8);
                const __half2* vh = (const __half2*)&vv;
#pragma unroll
                for (int j = 0; j < 4; j++) {
                    float2 f = __half22float2(vh[j]);
                    acc[c4 * 8 + 2*j]     += p * f.x;
                    acc[c4 * 8 + 2*j + 1] += p * f.y;
                }
            }
        }
        // store 32 halves into resident A smem: row t, cols h*32..h*32+31
#pragma unroll
        for (int j = 0; j < 16; j++) {
            __half2 hv = __floats2half2_rn(acc[2*j] * inv, acc[2*j + 1] * inv);
            As[t * LDA_U + h * 16 + j] = *(uint32_t*)&hv;
        }
    }
    __syncthreads();

    // ---- mainloop: 8 chunks of BK=32 over K=256 ----
    float d[4][8][4];
#pragma unroll
    for (int mt = 0; mt < 4; mt++)
#pragma unroll
        for (int nt = 0; nt < 8; nt++)
#pragma unroll
            for (int j = 0; j < 4; j++) d[mt][nt][j] = 0.0f;

    for (int c = 0; c < 8; c++) {
        const int buf = c & 1;
        if (c + 1 < 8) {
            const int nb  = (c + 1) & 1;
            const int k0g = (c + 1) * BK;
#pragma unroll
            for (int it = 0; it < 4; it++) {
                int row = brow + it * 64;
                cp_async16(Bs_u + (uint32_t)((nb * PBS_U + row * LDU + bc4) * 4),
                           Bw + (size_t)row * DIM + k0g + bc4 * 2);
            }
            cp_commit();
            cp_wait<1>();
        } else {
            cp_wait<0>();
        }
        __syncthreads();

        const uint32_t Bb = Bs_u + (uint32_t)(buf * PBS_U) * 4;

#pragma unroll
        for (int ks = 0; ks < 2; ks++) {
            const int koA = c * 16 + ks * 8;    // u32 offset within As row
            const int koB = ks * 8;
            uint32_t a[4][4];
#pragma unroll
            for (int mt = 0; mt < 4; mt++) {
                uint32_t addr = As_u + (uint32_t)(
                    (m_off + mt * 16 + a_row) * LDA_U + koA + a_kof) * 4;
                ldm_x4(a[mt][0], a[mt][1], a[mt][2], a[mt][3], addr);
            }
            uint32_t b[8][2];
#pragma unroll
            for (int np = 0; np < 4; np++) {
                uint32_t addr = Bb + (uint32_t)(
                    (n_off + np * 16 + b_row) * LDU + koB + b_kof) * 4;
                ldm_x4(b[2*np][0], b[2*np][1], b[2*np+1][0], b[2*np+1][1], addr);
            }
#pragma unroll
            for (int mt = 0; mt < 4; mt++)
#pragma unroll
                for (int nt = 0; nt < 8; nt++)
                    mma_f16(d[mt][nt][0], d[mt][nt][1], d[mt][nt][2], d[mt][nt][3],
                            a[mt][0], a[mt][1], a[mt][2], a[mt][3],
                            b[nt][0], b[nt][1]);
        }
        __syncthreads();
    }

    // ---- epilogue pass 1: y = d + bias + x; write y; row partial sums ----
    float bvx[8], bvy[8];
#pragma unroll
    for (int nt = 0; nt < 8; nt++) {
        const int n = n_off + nt * 8 + 2 * tg;
        const float2 bv = *(const float2*)&bias[n];
        bvx[nt] = bv.x; bvy[nt] = bv.y;
    }

#pragma unroll
    for (int mt = 0; mt < 4; mt++) {
#pragma unroll
        for (int half_i = 0; half_i < 2; half_i++) {
            const int lrow = m_off + mt * 16 + gid + half_i * 8;  // 0..127
            const int m = bm + lrow;
            float srow = 0.0f, qrow = 0.0f;
#pragma unroll
            for (int nt = 0; nt < 8; nt++) {
                const int n = n_off + nt * 8 + 2 * tg;
                const float2 r = *(const float2*)&x[(size_t)m * DIM + n];
                float yx = d[mt][nt][half_i * 2 + 0] + bvx[nt] + r.x;
                float yy = d[mt][nt][half_i * 2 + 1] + bvy[nt] + r.y;
                d[mt][nt][half_i * 2 + 0] = yx;    // keep y in regs for pass 2
                d[mt][nt][half_i * 2 + 1] = yy;
                float2 v; v.x = yx; v.y = yy;
                *(float2*)&y[(size_t)m * DIM + n] = v;
                srow += yx + yy;
                qrow += yx * yx + yy * yy;
            }
            srow += __shfl_xor_sync(0xffffffffu, srow, 1);
            srow += __shfl_xor_sync(0xffffffffu, srow, 2);
            qrow += __shfl_xor_sync(0xffffffffu, qrow, 1);
            qrow += __shfl_xor_sync(0xffffffffu, qrow, 2);
            if (tg == 0) { float2 p; p.x = srow; p.y = qrow; red[lrow * 4 + wn] = p; }
        }
    }
    __syncthreads();

    // ---- epilogue pass 2: LN2 -> xn (half) ----
#pragma unroll
    for (int mt = 0; mt < 4; mt++) {
#pragma unroll
        for (int half_i = 0; half_i < 2; half_i++) {
            const int lrow = m_off + mt * 16 + gid + half_i * 8;
            const int m = bm + lrow;
            float2 p0 = red[lrow * 4 + 0], p1 = red[lrow * 4 + 1];
            float2 p2 = red[lrow * 4 + 2], p3 = red[lrow * 4 + 3];
            float S = p0.x + p1.x + p2.x + p3.x;
            float Q = p0.y + p1.y + p2.y + p3.y;
            float mean = S * (1.0f / 256.0f);
            float var  = Q * (1.0f / 256.0f) - mean * mean;
            float inv  = rsqrtf(var + 1e-5f);
#pragma unroll
            for (int nt = 0; nt < 8; nt++) {
                const int n = n_off + nt * 8 + 2 * tg;
                const float2 gg = *(const float2*)&ln2g[n];
                const float2 bb = *(const float2*)&ln2b[n];
                float ox = (d[mt][nt][half_i * 2 + 0] - mean) * inv * gg.x + bb.x;
                float oy = (d[mt][nt][half_i * 2 + 1] - mean) * inv * gg.y + bb.y;
                *(__half2*)&xn[(size_t)m * DIM + n] = __floats2half2_rn(ox, oy);
            }
        }
    }
}

// ===================== weight rounding (all four, one launch) ===============
__global__ void __launch_bounds__(256) round_w_all(
    const float* __restrict__ qkv_w, const float* __restrict__ proj_w,
    const float* __restrict__ ffn_w1, const float* __restrict__ ffn_w2,
    __half* __restrict__ dst)
{
    int i = blockIdx.x * 256 + threadIdx.x;          // float4 index, 196608 total
    const float* src;
    int local;
    if (i < 49152)       { src = qkv_w;  local = i;           }
    else if (i < 65536)  { src = proj_w; local = i - 49152;   }
    else if (i < 131072) { src = ffn_w1; local = i - 65536;   }
    else                 { src = ffn_w2; local = i - 131072;  }
    float4 v = ((const float4*)src)[local];
    __half2 lo = __floats2half2_rn(v.x, v.y);
    __half2 hi = __floats2half2_rn(v.z, v.w);
    uint2 o; o.x = *(uint32_t*)&lo; o.y = *(uint32_t*)&hi;
    ((uint2*)dst)[i] = o;
}

// ===================== LayerNorm (LN1; one warp per 256-float row) ==========
__global__ void __launch_bounds__(256) ln_kernel(
    const float* __restrict__ x, const float* __restrict__ g,
    const float* __restrict__ b, __half* __restrict__ out)
{
    int row  = (blockIdx.x * blockDim.x + threadIdx.x) >> 5;
    int lane = threadIdx.x & 31;
    const float4* xr = (const float4*)(x + (size_t)row * DIM);
    float4 v0 = xr[lane];
    float4 v1 = xr[lane + 32];

    float s = v0.x + v0.y + v0.z + v0.w + v1.x + v1.y + v1.z + v1.w;
    float q = v0.x*v0.x + v0.y*v0.y + v0.z*v0.z + v0.w*v0.w
            + v1.x*v1.x + v1.y*v1.y + v1.z*v1.z + v1.w*v1.w;
#pragma unroll
    for (int o = 16; o > 0; o >>= 1) {
        s += __shfl_xor_sync(0xffffffffu, s, o);
        q += __shfl_xor_sync(0xffffffffu, q, o);
    }
    float mean = s * (1.0f / 256.0f);
    float var  = q * (1.0f / 256.0f) - mean * mean;
    float inv  = rsqrtf(var + 1e-5f);

    const float4* g4 = (const float4*)g;
    const float4* b4 = (const float4*)b;
    float4 ga = g4[lane], gb = g4[lane + 32];
    float4 ba = b4[lane], bb = b4[lane + 32];

    __half2 h0 = __floats2half2_rn((v0.x - mean) * inv * ga.x + ba.x,
                                   (v0.y - mean) * inv * ga.y + ba.y);
    __half2 h1 = __floats2half2_rn((v0.z - mean) * inv * ga.z + ba.z,
                                   (v0.w - mean) * inv * ga.w + ba.w);
    __half2 h2 = __floats2half2_rn((v1.x - mean) * inv * gb.x + bb.x,
                                   (v1.y - mean) * inv * gb.y + bb.y);
    __half2 h3 = __floats2half2_rn((v1.z - mean) * inv * gb.z + bb.z,
                                   (v1.w - mean) * inv * gb.w + bb.w);

    __half* orow = out + (size_t)row * DIM;
    uint2 p0; p0.x = *(uint32_t*)&h0; p0.y = *(uint32_t*)&h1;
    uint2 p1; p1.x = *(uint32_t*)&h2; p1.y = *(uint32_t*)&h3;
    *(uint2*)(orow + lane * 4)       = p0;
    *(uint2*)(orow + 128 + lane * 4) = p1;
}

// ===================== Launch ===============================================
extern "C" void kernel_launch(void* const* d_in, const int* in_sizes, int n_in,
                              void* d_out, int out_size)
{
    const float* x      = (const float*)d_in[0];
    const float* ln1_g  = (const float*)d_in[1];
    const float* ln1_b  = (const float*)d_in[2];
    const float* qkv_w  = (const float*)d_in[3];
    const float* qkv_b  = (const float*)d_in[4];
    const float* proj_w = (const float*)d_in[5];
    const float* proj_b = (const float*)d_in[6];
    const float* ln2_g  = (const float*)d_in[7];
    const float* ln2_b  = (const float*)d_in[8];
    const float* ffn_w1 = (const float*)d_in[9];
    const float* ffn_b1 = (const float*)d_in[10];
    const float* ffn_w2 = (const float*)d_in[11];
    const float* ffn_b2 = (const float*)d_in[12];

    __half *xn, *qkv, *h, *w;
    float  *y;
    cudaGetSymbolAddress((void**)&xn,   g_xn);
    cudaGetSymbolAddress((void**)&qkv,  g_qkv);
    cudaGetSymbolAddress((void**)&y,    g_y);
    cudaGetSymbolAddress((void**)&h,    g_h);
    cudaGetSymbolAddress((void**)&w,    g_w);
    float* out = (float*)d_out;

    cudaFuncSetAttribute(fused_attn_proj_ln,
                         cudaFuncAttributeMaxDynamicSharedMemorySize, FUSED_SMEM);

    const int MROWS = TOKENS / TILE;   // 512

    // 0) round all weights to fp16 in one launch
    round_w_all<<<196608 / 256, 256>>>(qkv_w, proj_w, ffn_w1, ffn_w2, w);

    // 1) LN1 (half out)
    ln_kernel<<<TOKENS / 8, 256>>>(x, ln1_g, ln1_b, xn);
    // 2) QKV = xn @ qkv_w^T + qkv_b          [65536, 768] half
    mma_gemm<0, __half><<<dim3(768 / TILE, MROWS), 128>>>(
        xn, w + W_QKV, qkv_b, nullptr, qkv, DIM, 3 * DIM);
    // 3+4+5) attention + proj (+x residual) + LN2, fused
    fused_attn_proj_ln<<<MROWS, 256, FUSED_SMEM>>>(
        qkv, w + W_PROJ, proj_b, x, ln2_g, ln2_b, y, xn);
    // 6) h = relu(xn @ ffn_w1^T + ffn_b1)    [65536, 1024] half
    mma_gemm<1, __half><<<dim3(FFNDIM / TILE, MROWS), 128>>>(
        xn, w + W_FFN1, ffn_b1, nullptr, h, DIM, FFNDIM);
    // 7) out = y + h @ ffn_w2^T + ffn_b2     [65536, 256] f32
    mma_gemm<2, float><<<dim3(DIM / TILE, MROWS), 128>>>(
        h, w + W_FFN2, ffn_b2, y, out, FFNDIM, DIM);
}

// round 11
// speedup vs baseline: 1.2500x; 1.0611x over previous
#include <cuda_runtime.h>
#include <cuda_fp16.h>
#include <cstdint>

// ---------------------------------------------------------------------------
// SimpleMaxViTBlock: LN1 -> per-token head-mixing attention -> +res
//                    -> LN2 -> FFN -> +res
// GEMMs: mma.sync m16n8k16 fp16, fp32 accum (R8 datapath: measured at the
// 512 MAC/cyc/SM legacy-HMMA pipe floor). R11: reverted fusions; smem-free
// attention kernel; round_w+LN1 merged into one launch.
// ---------------------------------------------------------------------------

constexpr int TOKENS = 65536;
constexpr int DIM    = 256;
constexpr int HEADS  = 8;
constexpr int HD     = 32;
constexpr int FFNDIM = 1024;

// Scratch (device globals: allocation-free rule)
__device__ __half g_xn  [ (size_t)TOKENS * DIM    ];
__device__ __half g_qkv [ (size_t)TOKENS * 3*DIM  ];
__device__ __half g_attn[ (size_t)TOKENS * DIM    ];
__device__ float  g_y   [ (size_t)TOKENS * DIM    ];
__device__ __half g_h   [ (size_t)TOKENS * FFNDIM ];
__device__ __half g_w   [ 786432 ];   // fp16-rounded weights

constexpr int W_QKV  = 0;
constexpr int W_PROJ = 196608;
constexpr int W_FFN1 = 262144;
constexpr int W_FFN2 = 524288;

// ===================== helpers ==============================================
__device__ __forceinline__ uint32_t smem_u32(const void* p) {
    uint32_t a;
    asm("{ .reg .u64 t; cvta.to.shared.u64 t, %1; cvt.u32.u64 %0, t; }"
        : "=r"(a) : "l"(p));
    return a;
}
__device__ __forceinline__ void cp_async16(uint32_t saddr, const void* gaddr) {
    asm volatile("cp.async.cg.shared.global [%0], [%1], 16;"
                 :: "r"(saddr), "l"(gaddr) : "memory");
}
__device__ __forceinline__ void cp_commit() {
    asm volatile("cp.async.commit_group;" ::: "memory");
}
template<int N>
__device__ __forceinline__ void cp_wait() {
    asm volatile("cp.async.wait_group %0;" :: "n"(N) : "memory");
}
__device__ __forceinline__ void ldm_x4(uint32_t& r0, uint32_t& r1,
                                       uint32_t& r2, uint32_t& r3, uint32_t addr) {
    asm volatile("ldmatrix.sync.aligned.m8n8.x4.shared.b16 {%0,%1,%2,%3}, [%4];"
                 : "=r"(r0), "=r"(r1), "=r"(r2), "=r"(r3) : "r"(addr));
}
__device__ __forceinline__ void mma_f16(
    float& d0, float& d1, float& d2, float& d3,
    uint32_t a0, uint32_t a1, uint32_t a2, uint32_t a3,
    uint32_t b0, uint32_t b1)
{
    asm volatile(
        "mma.sync.aligned.m16n8k16.row.col.f32.f16.f16.f32 "
        "{%0,%1,%2,%3}, {%4,%5,%6,%7}, {%8,%9}, {%0,%1,%2,%3};"
        : "+f"(d0), "+f"(d1), "+f"(d2), "+f"(d3)
        : "r"(a0), "r"(a1), "r"(a2), "r"(a3), "r"(b0), "r"(b1));
}

// ===================== fp16 mma.sync GEMM (R8 datapath) =====================
// C[m,n] = epi( sum_k A[m,k]*B[n,k] + bias[n] [+res] )
// CTA 128x128, BK=32 halves, double-buffered cp.async, 4 warps (2x2),
// warp tile 64x64, ldmatrix fragments, fp32 accumulators, 2 CTAs/SM.
// MODE: 0 = bias -> half out, 1 = bias+relu -> half out, 2 = bias+res -> f32
constexpr int TILE  = 128;
constexpr int BK    = 32;
constexpr int LDU   = 20;              // u32 per smem row (= 40 halves, 80B)
constexpr int SLABU = TILE * LDU;      // 2560 u32 per stage per matrix

template<int MODE, typename OutT>
__global__ void __launch_bounds__(128, 2) mma_gemm(
    const __half* __restrict__ A, const __half* __restrict__ B,
    const float* __restrict__ bias, const float* __restrict__ res,
    OutT* __restrict__ C, int K, int N)
{
    __shared__ __align__(16) uint32_t sm[4 * SLABU];   // 40960 B
    uint32_t* As = sm;
    uint32_t* Bs = sm + 2 * SLABU;
    const uint32_t As_u = smem_u32(As);
    const uint32_t Bs_u = smem_u32(Bs);

    const int tid  = threadIdx.x;
    const int wid  = tid >> 5;
    const int lane = tid & 31;
    const int gid  = lane >> 2;
    const int tg   = lane & 3;

    const int bm = blockIdx.y * TILE;
    const int bn = blockIdx.x * TILE;
    const int m_off = (wid >> 1) * 64;
    const int n_off = (wid & 1) * 64;

    const int lrow8 = lane & 7;
    const int a_row = (lrow8 + ((lane >> 3) & 1) * 8);
    const int a_kof = (lane >> 4) * 4;
    const int b_row = (lrow8 + ((lane >> 4) & 1) * 8);
    const int b_kof = ((lane >> 3) & 1) * 4;

    const int crow = tid >> 2;
    const int cc4  = (tid & 3) * 4;

    float d[4][8][4];
#pragma unroll
    for (int mt = 0; mt < 4; mt++)
#pragma unroll
        for (int nt = 0; nt < 8; nt++)
#pragma unroll
            for (int j = 0; j < 4; j++) d[mt][nt][j] = 0.0f;

    const int C_CHUNKS = K / BK;

    {
#pragma unroll
        for (int it = 0; it < 4; it++) {
            int row = crow + it * 32;
            cp_async16(As_u + (uint32_t)(row * LDU + cc4) * 4,
                       A + (size_t)(bm + row) * K + cc4 * 2);
            cp_async16(Bs_u + (uint32_t)(row * LDU + cc4) * 4,
                       B + (size_t)(bn + row) * K + cc4 * 2);
        }
        cp_commit();
    }

    for (int c = 0; c < C_CHUNKS; c++) {
        const int buf = c & 1;
        if (c + 1 < C_CHUNKS) {
            const int nb  = (c + 1) & 1;
            const int k0g = (c + 1) * BK;
#pragma unroll
            for (int it = 0; it < 4; it++) {
                int row = crow + it * 32;
                cp_async16(As_u + (uint32_t)((nb * SLABU + row * LDU + cc4) * 4),
                           A + (size_t)(bm + row) * K + k0g + cc4 * 2);
                cp_async16(Bs_u + (uint32_t)((nb * SLABU + row * LDU + cc4) * 4),
                           B + (size_t)(bn + row) * K + k0g + cc4 * 2);
            }
            cp_commit();
            cp_wait<1>();
        } else {
            cp_wait<0>();
        }
        __syncthreads();

        const uint32_t Ab = As_u + (uint32_t)(buf * SLABU) * 4;
        const uint32_t Bb = Bs_u + (uint32_t)(buf * SLABU) * 4;

#pragma unroll
        for (int ks = 0; ks < 2; ks++) {
            const int ko = ks * 8;
            uint32_t a[4][4];
#pragma unroll
            for (int mt = 0; mt < 4; mt++) {
                uint32_t addr = Ab + (uint32_t)(
                    (m_off + mt * 16 + a_row) * LDU + ko + a_kof) * 4;
                ldm_x4(a[mt][0], a[mt][1], a[mt][2], a[mt][3], addr);
            }
            uint32_t b[8][2];
#pragma unroll
            for (int np = 0; np < 4; np++) {
                uint32_t addr = Bb + (uint32_t)(
                    (n_off + np * 16 + b_row) * LDU + ko + b_kof) * 4;
                ldm_x4(b[2*np][0], b[2*np][1], b[2*np+1][0], b[2*np+1][1], addr);
            }
#pragma unroll
            for (int mt = 0; mt < 4; mt++)
#pragma unroll
                for (int nt = 0; nt < 8; nt++)
                    mma_f16(d[mt][nt][0], d[mt][nt][1], d[mt][nt][2], d[mt][nt][3],
                            a[mt][0], a[mt][1], a[mt][2], a[mt][3],
                            b[nt][0], b[nt][1]);
        }
        __syncthreads();
    }

#pragma unroll
    for (int nt = 0; nt < 8; nt++) {
        const int n = bn + n_off + nt * 8 + 2 * tg;
        const float2 bv = *(const float2*)&bias[n];
#pragma unroll
        for (int mt = 0; mt < 4; mt++) {
            const int m0 = bm + m_off + mt * 16 + gid;
#pragma unroll
            for (int half_i = 0; half_i < 2; half_i++) {
                const int m = m0 + half_i * 8;
                float vx = d[mt][nt][half_i * 2 + 0] + bv.x;
                float vy = d[mt][nt][half_i * 2 + 1] + bv.y;
                if (MODE == 1) { vx = fmaxf(vx, 0.f); vy = fmaxf(vy, 0.f); }
                if (MODE == 2) {
                    const float2 r = *(const float2*)&res[(size_t)m * N + n];
                    float2 v; v.x = vx + r.x; v.y = vy + r.y;
                    *(float2*)&((float*)C)[(size_t)m * N + n] = v;
                } else {
                    *(__half2*)&((__half*)C)[(size_t)m * N + n] =
                        __floats2half2_rn(vx, vy);
                }
            }
        }
    }
}

// ===================== LayerNorm row helper =================================
__device__ __forceinline__ void ln_row(
    const float* __restrict__ x, const float* __restrict__ g,
    const float* __restrict__ b, __half* __restrict__ out,
    int row, int lane)
{
    const float4* xr = (const float4*)(x + (size_t)row * DIM);
    float4 v0 = xr[lane];
    float4 v1 = xr[lane + 32];

    float s = v0.x + v0.y + v0.z + v0.w + v1.x + v1.y + v1.z + v1.w;
    float q = v0.x*v0.x + v0.y*v0.y + v0.z*v0.z + v0.w*v0.w
            + v1.x*v1.x + v1.y*v1.y + v1.z*v1.z + v1.w*v1.w;
#pragma unroll
    for (int o = 16; o > 0; o >>= 1) {
        s += __shfl_xor_sync(0xffffffffu, s, o);
        q += __shfl_xor_sync(0xffffffffu, q, o);
    }
    float mean = s * (1.0f / 256.0f);
    float var  = q * (1.0f / 256.0f) - mean * mean;
    float inv  = rsqrtf(var + 1e-5f);

    const float4* g4 = (const float4*)g;
    const float4* b4 = (const float4*)b;
    float4 ga = g4[lane], gb = g4[lane + 32];
    float4 ba = b4[lane], bb = b4[lane + 32];

    __half2 h0 = __floats2half2_rn((v0.x - mean) * inv * ga.x + ba.x,
                                   (v0.y - mean) * inv * ga.y + ba.y);
    __half2 h1 = __floats2half2_rn((v0.z - mean) * inv * ga.z + ba.z,
                                   (v0.w - mean) * inv * ga.w + ba.w);
    __half2 h2 = __floats2half2_rn((v1.x - mean) * inv * gb.x + bb.x,
                                   (v1.y - mean) * inv * gb.y + bb.y);
    __half2 h3 = __floats2half2_rn((v1.z - mean) * inv * gb.z + bb.z,
                                   (v1.w - mean) * inv * gb.w + bb.w);

    __half* orow = out + (size_t)row * DIM;
    uint2 p0; p0.x = *(uint32_t*)&h0; p0.y = *(uint32_t*)&h1;
    uint2 p1; p1.x = *(uint32_t*)&h2; p1.y = *(uint32_t*)&h3;
    *(uint2*)(orow + lane * 4)       = p0;
    *(uint2*)(orow + 128 + lane * 4) = p1;
}

// ===================== init: weight rounding + LN1, one launch ==============
// blocks [0, 768): round 196608 float4s of weights to fp16
// blocks [768, 768+8192): LN1 (one warp per row, 8 rows per block)
__global__ void __launch_bounds__(256) init_kernel(
    const float* __restrict__ qkv_w, const float* __restrict__ proj_w,
    const float* __restrict__ ffn_w1, const float* __restrict__ ffn_w2,
    __half* __restrict__ wdst,
    const float* __restrict__ x, const float* __restrict__ ln1g,
    const float* __restrict__ ln1b, __half* __restrict__ xn)
{
    if (blockIdx.x < 768) {
        int i = blockIdx.x * 256 + threadIdx.x;      // float4 index
        const float* src;
        int local;
        if (i < 49152)       { src = qkv_w;  local = i;           }
        else if (i < 65536)  { src = proj_w; local = i - 49152;   }
        else if (i < 131072) { src = ffn_w1; local = i - 65536;   }
        else                 { src = ffn_w2; local = i - 131072;  }
        float4 v = ((const float4*)src)[local];
        __half2 lo = __floats2half2_rn(v.x, v.y);
        __half2 hi = __floats2half2_rn(v.z, v.w);
        uint2 o; o.x = *(uint32_t*)&lo; o.y = *(uint32_t*)&hi;
        ((uint2*)wdst)[i] = o;
    } else {
        int row = ((blockIdx.x - 768) * 256 + threadIdx.x) >> 5;
        ln_row(x, ln1g, ln1b, xn, row, threadIdx.x & 31);
    }
}

// ===================== LayerNorm (LN2) ======================================
__global__ void __launch_bounds__(256) ln_kernel(
    const float* __restrict__ x, const float* __restrict__ g,
    const float* __restrict__ b, __half* __restrict__ out)
{
    int row  = (blockIdx.x * blockDim.x + threadIdx.x) >> 5;
    ln_row(x, g, b, out, row, threadIdx.x & 31);
}

// ===================== Per-token head-mixing attention ======================
// One thread per (token, head); no smem, no syncthreads.
// Lanes 0-7 of a token share K/V rows (L1 broadcast); q reads coalesce.
__global__ void __launch_bounds__(256) attn_kernel(
    const __half* __restrict__ qkv, __half* __restrict__ out)
{
    const int idx = blockIdx.x * 256 + threadIdx.x;  // (token, head)
    const int t = idx >> 3;
    const int h = idx & 7;
    const __half* base = qkv + (size_t)t * 768;

    float q[HD];
#pragma unroll
    for (int c4 = 0; c4 < 4; c4++) {
        uint4 qv = *(const uint4*)(base + h * HD + c4 * 8);
        const __half2* qh = (const __half2*)&qv;
#pragma unroll
        for (int j = 0; j < 4; j++) {
            float2 f = __half22float2(qh[j]);
            q[c4 * 8 + 2*j] = f.x; q[c4 * 8 + 2*j + 1] = f.y;
        }
    }

    const float scale = 0.17677669529663688f;   // 1/sqrt(32)
    float sc[HEADS];
    float mx = -1e30f;
#pragma unroll
    for (int g = 0; g < HEADS; g++) {
        float s = 0.0f;
#pragma unroll
        for (int c4 = 0; c4 < 4; c4++) {
            uint4 kv = *(const uint4*)(base + 256 + g * HD + c4 * 8);
            const __half2* kh = (const __half2*)&kv;
#pragma unroll
            for (int j = 0; j < 4; j++) {
                float2 f = __half22float2(kh[j]);
                s += q[c4 * 8 + 2*j] * f.x + q[c4 * 8 + 2*j + 1] * f.y;
            }
        }
        s *= scale;
        sc[g] = s;
        mx = fmaxf(mx, s);
    }
    float sum = 0.0f;
#pragma unroll
    for (int g = 0; g < HEADS; g++) {
        float e = __expf(sc[g] - mx);
        sc[g] = e;
        sum += e;
    }
    const float inv = 1.0f / sum;

    float acc[HD];
#pragma unroll
    for (int d0 = 0; d0 < HD; d0++) acc[d0] = 0.0f;
#pragma unroll
    for (int g = 0; g < HEADS; g++) {
        const float p = sc[g];
#pragma unroll
        for (int c4 = 0; c4 < 4; c4++) {
            uint4 vv = *(const uint4*)(base + 512 + g * HD + c4 * 8);
            const __half2* vh = (const __half2*)&vv;
#pragma unroll
            for (int j = 0; j < 4; j++) {
                float2 f = __half22float2(vh[j]);
                acc[c4 * 8 + 2*j]     += p * f.x;
                acc[c4 * 8 + 2*j + 1] += p * f.y;
            }
        }
    }

    __half* orow = out + (size_t)t * DIM + h * HD;
#pragma unroll
    for (int c4 = 0; c4 < 4; c4++) {
        __half2 o0 = __floats2half2_rn(acc[c4*8+0] * inv, acc[c4*8+1] * inv);
        __half2 o1 = __floats2half2_rn(acc[c4*8+2] * inv, acc[c4*8+3] * inv);
        __half2 o2 = __floats2half2_rn(acc[c4*8+4] * inv, acc[c4*8+5] * inv);
        __half2 o3 = __floats2half2_rn(acc[c4*8+6] * inv, acc[c4*8+7] * inv);
        uint4 p;
        p.x = *(uint32_t*)&o0; p.y = *(uint32_t*)&o1;
        p.z = *(uint32_t*)&o2; p.w = *(uint32_t*)&o3;
        *(uint4*)(orow + c4 * 8) = p;
    }
}

// ===================== Launch ===============================================
extern "C" void kernel_launch(void* const* d_in, const int* in_sizes, int n_in,
                              void* d_out, int out_size)
{
    const float* x      = (const float*)d_in[0];
    const float* ln1_g  = (const float*)d_in[1];
    const float* ln1_b  = (const float*)d_in[2];
    const float* qkv_w  = (const float*)d_in[3];
    const float* qkv_b  = (const float*)d_in[4];
    const float* proj_w = (const float*)d_in[5];
    const float* proj_b = (const float*)d_in[6];
    const float* ln2_g  = (const float*)d_in[7];
    const float* ln2_b  = (const float*)d_in[8];
    const float* ffn_w1 = (const float*)d_in[9];
    const float* ffn_b1 = (const float*)d_in[10];
    const float* ffn_w2 = (const float*)d_in[11];
    const float* ffn_b2 = (const float*)d_in[12];

    __half *xn, *qkv, *attn, *h, *w;
    float  *y;
    cudaGetSymbolAddress((void**)&xn,   g_xn);
    cudaGetSymbolAddress((void**)&qkv,  g_qkv);
    cudaGetSymbolAddress((void**)&attn, g_attn);
    cudaGetSymbolAddress((void**)&y,    g_y);
    cudaGetSymbolAddress((void**)&h,    g_h);
    cudaGetSymbolAddress((void**)&w,    g_w);
    float* out = (float*)d_out;

    const int MROWS = TOKENS / TILE;   // 512

    // 0+1) weight rounding + LN1 in one launch
    init_kernel<<<768 + TOKENS / 8, 256>>>(
        qkv_w, proj_w, ffn_w1, ffn_w2, w, x, ln1_g, ln1_b, xn);
    // 2) QKV = xn @ qkv_w^T + qkv_b          [65536, 768] half
    mma_gemm<0, __half><<<dim3(768 / TILE, MROWS), 128>>>(
        xn, w + W_QKV, qkv_b, nullptr, qkv, DIM, 3 * DIM);
    // 3) per-token head-mixing attention (half out)
    attn_kernel<<<TOKENS * 8 / 256, 256>>>(qkv, attn);
    // 4) y = x + attn @ proj_w^T + proj_b    [65536, 256] f32
    mma_gemm<2, float><<<dim3(DIM / TILE, MROWS), 128>>>(
        attn, w + W_PROJ, proj_b, x, y, DIM, DIM);
    // 5) LN2 (half out)
    ln_kernel<<<TOKENS / 8, 256>>>(y, ln2_g, ln2_b, xn);
    // 6) h = relu(xn @ ffn_w1^T + ffn_b1)    [65536, 1024] half
    mma_gemm<1, __half><<<dim3(FFNDIM / TILE, MROWS), 128>>>(
        xn, w + W_FFN1, ffn_b1, nullptr, h, DIM, FFNDIM);
    // 7) out = y + h @ ffn_w2^T + ffn_b2     [65536, 256] f32
    mma_gemm<2, float><<<dim3(DIM / TILE, MROWS), 128>>>(
        h, w + W_FFN2, ffn_b2, y, out, FFNDIM, DIM);
}

// round 12
// speedup vs baseline: 1.2544x; 1.0035x over previous
#include <cuda_runtime.h>
#include <cuda_fp16.h>
#include <cstdint>

// ---------------------------------------------------------------------------
// SimpleMaxViTBlock: LN1 -> per-token head-mixing attention -> +res
//                    -> LN2 -> FFN -> +res
// GEMMs: mma.sync m16n8k16 fp16, fp32 accum, ldmatrix fragments, 4 warps
// (2x2) x 64x64 warp tiles, THREE-stage cp.async pipeline (R12), 2 CTAs/SM.
// ---------------------------------------------------------------------------

constexpr int TOKENS = 65536;
constexpr int DIM    = 256;
constexpr int HEADS  = 8;
constexpr int HD     = 32;
constexpr int FFNDIM = 1024;

// Scratch (device globals: allocation-free rule)
__device__ __half g_xn  [ (size_t)TOKENS * DIM    ];
__device__ __half g_qkv [ (size_t)TOKENS * 3*DIM  ];
__device__ __half g_attn[ (size_t)TOKENS * DIM    ];
__device__ float  g_y   [ (size_t)TOKENS * DIM    ];
__device__ __half g_h   [ (size_t)TOKENS * FFNDIM ];
__device__ __half g_w   [ 786432 ];   // fp16-rounded weights

constexpr int W_QKV  = 0;
constexpr int W_PROJ = 196608;
constexpr int W_FFN1 = 262144;
constexpr int W_FFN2 = 524288;

// ===================== helpers ==============================================
__device__ __forceinline__ uint32_t smem_u32(const void* p) {
    uint32_t a;
    asm("{ .reg .u64 t; cvta.to.shared.u64 t, %1; cvt.u32.u64 %0, t; }"
        : "=r"(a) : "l"(p));
    return a;
}
__device__ __forceinline__ void cp_async16(uint32_t saddr, const void* gaddr) {
    asm volatile("cp.async.cg.shared.global [%0], [%1], 16;"
                 :: "r"(saddr), "l"(gaddr) : "memory");
}
__device__ __forceinline__ void cp_commit() {
    asm volatile("cp.async.commit_group;" ::: "memory");
}
template<int N>
__device__ __forceinline__ void cp_wait() {
    asm volatile("cp.async.wait_group %0;" :: "n"(N) : "memory");
}
__device__ __forceinline__ void ldm_x4(uint32_t& r0, uint32_t& r1,
                                       uint32_t& r2, uint32_t& r3, uint32_t addr) {
    asm volatile("ldmatrix.sync.aligned.m8n8.x4.shared.b16 {%0,%1,%2,%3}, [%4];"
                 : "=r"(r0), "=r"(r1), "=r"(r2), "=r"(r3) : "r"(addr));
}
__device__ __forceinline__ void mma_f16(
    float& d0, float& d1, float& d2, float& d3,
    uint32_t a0, uint32_t a1, uint32_t a2, uint32_t a3,
    uint32_t b0, uint32_t b1)
{
    asm volatile(
        "mma.sync.aligned.m16n8k16.row.col.f32.f16.f16.f32 "
        "{%0,%1,%2,%3}, {%4,%5,%6,%7}, {%8,%9}, {%0,%1,%2,%3};"
        : "+f"(d0), "+f"(d1), "+f"(d2), "+f"(d3)
        : "r"(a0), "r"(a1), "r"(a2), "r"(a3), "r"(b0), "r"(b1));
}

// ===================== fp16 mma.sync GEMM (3-stage pipeline) ================
// C[m,n] = epi( sum_k A[m,k]*B[n,k] + bias[n] [+res] )
// CTA 128x128, BK=32 halves, 3-stage cp.async, 4 warps (2x2), warp 64x64,
// ldmatrix fragments, fp32 accumulators, 2 CTAs/SM (dynamic smem 60KB).
// MODE: 0 = bias -> half out, 1 = bias+relu -> half out, 2 = bias+res -> f32
constexpr int TILE  = 128;
constexpr int BK    = 32;
constexpr int LDU   = 20;              // u32 per smem row (= 40 halves, 80B)
constexpr int SLABU = TILE * LDU;      // 2560 u32 per stage per matrix
constexpr int GEMM_SMEM = 6 * SLABU * 4;   // 61440 B (3 stages x A,B)

template<int MODE, typename OutT>
__global__ void __launch_bounds__(128, 2) mma_gemm(
    const __half* __restrict__ A, const __half* __restrict__ B,
    const float* __restrict__ bias, const float* __restrict__ res,
    OutT* __restrict__ C, int K, int N)
{
    extern __shared__ uint32_t sm[];
    const uint32_t As_u = smem_u32(sm);                 // [3][128][20]
    const uint32_t Bs_u = As_u + 3 * SLABU * 4;         // [3][128][20]

    const int tid  = threadIdx.x;
    const int wid  = tid >> 5;
    const int lane = tid & 31;
    const int gid  = lane >> 2;
    const int tg   = lane & 3;

    const int bm = blockIdx.y * TILE;
    const int bn = blockIdx.x * TILE;
    const int m_off = (wid >> 1) * 64;
    const int n_off = (wid & 1) * 64;

    const int lrow8 = lane & 7;
    const int a_row = (lrow8 + ((lane >> 3) & 1) * 8);
    const int a_kof = (lane >> 4) * 4;
    const int b_row = (lrow8 + ((lane >> 4) & 1) * 8);
    const int b_kof = ((lane >> 3) & 1) * 4;

    const int crow = tid >> 2;
    const int cc4  = (tid & 3) * 4;

    float d[4][8][4];
#pragma unroll
    for (int mt = 0; mt < 4; mt++)
#pragma unroll
        for (int nt = 0; nt < 8; nt++)
#pragma unroll
            for (int j = 0; j < 4; j++) d[mt][nt][j] = 0.0f;

    const int C_CHUNKS = K / BK;

    // issue chunk cc into stage s
    auto issue = [&](int cc, int s) {
        const int k0g = cc * BK;
        const uint32_t aofs = (uint32_t)(s * SLABU) * 4;
#pragma unroll
        for (int it = 0; it < 4; it++) {
            int row = crow + it * 32;
            cp_async16(As_u + aofs + (uint32_t)(row * LDU + cc4) * 4,
                       A + (size_t)(bm + row) * K + k0g + cc4 * 2);
            cp_async16(Bs_u + aofs + (uint32_t)(row * LDU + cc4) * 4,
                       B + (size_t)(bn + row) * K + k0g + cc4 * 2);
        }
        cp_commit();
    };

    issue(0, 0);
    if (C_CHUNKS > 1) issue(1, 1);

    int s_next = (C_CHUNKS > 1) ? 2 : 1;   // stage for the next issued chunk
    int s_cur  = 0;                         // stage holding chunk c

    for (int c = 0; c < C_CHUNKS; c++) {
        if (c + 2 < C_CHUNKS) {
            issue(c + 2, s_next);
            if (++s_next == 3) s_next = 0;
            cp_wait<2>();                   // chunks c+1, c+2 may be pending
        } else if (c + 1 < C_CHUNKS) {
            cp_wait<1>();
        } else {
            cp_wait<0>();
        }
        __syncthreads();

        const uint32_t Ab = As_u + (uint32_t)(s_cur * SLABU) * 4;
        const uint32_t Bb = Bs_u + (uint32_t)(s_cur * SLABU) * 4;
        if (++s_cur == 3) s_cur = 0;

#pragma unroll
        for (int ks = 0; ks < 2; ks++) {
            const int ko = ks * 8;
            uint32_t a[4][4];
#pragma unroll
            for (int mt = 0; mt < 4; mt++) {
                uint32_t addr = Ab + (uint32_t)(
                    (m_off + mt * 16 + a_row) * LDU + ko + a_kof) * 4;
                ldm_x4(a[mt][0], a[mt][1], a[mt][2], a[mt][3], addr);
            }
            uint32_t b[8][2];
#pragma unroll
            for (int np = 0; np < 4; np++) {
                uint32_t addr = Bb + (uint32_t)(
                    (n_off + np * 16 + b_row) * LDU + ko + b_kof) * 4;
                ldm_x4(b[2*np][0], b[2*np][1], b[2*np+1][0], b[2*np+1][1], addr);
            }
#pragma unroll
            for (int mt = 0; mt < 4; mt++)
#pragma unroll
                for (int nt = 0; nt < 8; nt++)
                    mma_f16(d[mt][nt][0], d[mt][nt][1], d[mt][nt][2], d[mt][nt][3],
                            a[mt][0], a[mt][1], a[mt][2], a[mt][3],
                            b[nt][0], b[nt][1]);
        }
        __syncthreads();
    }

#pragma unroll
    for (int nt = 0; nt < 8; nt++) {
        const int n = bn + n_off + nt * 8 + 2 * tg;
        const float2 bv = *(const float2*)&bias[n];
#pragma unroll
        for (int mt = 0; mt < 4; mt++) {
            const int m0 = bm + m_off + mt * 16 + gid;
#pragma unroll
            for (int half_i = 0; half_i < 2; half_i++) {
                const int m = m0 + half_i * 8;
                float vx = d[mt][nt][half_i * 2 + 0] + bv.x;
                float vy = d[mt][nt][half_i * 2 + 1] + bv.y;
                if (MODE == 1) { vx = fmaxf(vx, 0.f); vy = fmaxf(vy, 0.f); }
                if (MODE == 2) {
                    const float2 r = *(const float2*)&res[(size_t)m * N + n];
                    float2 v; v.x = vx + r.x; v.y = vy + r.y;
                    *(float2*)&((float*)C)[(size_t)m * N + n] = v;
                } else {
                    *(__half2*)&((__half*)C)[(size_t)m * N + n] =
                        __floats2half2_rn(vx, vy);
                }
            }
        }
    }
}

// ===================== LayerNorm row helper =================================
__device__ __forceinline__ void ln_row(
    const float* __restrict__ x, const float* __restrict__ g,
    const float* __restrict__ b, __half* __restrict__ out,
    int row, int lane)
{
    const float4* xr = (const float4*)(x + (size_t)row * DIM);
    float4 v0 = xr[lane];
    float4 v1 = xr[lane + 32];

    float s = v0.x + v0.y + v0.z + v0.w + v1.x + v1.y + v1.z + v1.w;
    float q = v0.x*v0.x + v0.y*v0.y + v0.z*v0.z + v0.w*v0.w
            + v1.x*v1.x + v1.y*v1.y + v1.z*v1.z + v1.w*v1.w;
#pragma unroll
    for (int o = 16; o > 0; o >>= 1) {
        s += __shfl_xor_sync(0xffffffffu, s, o);
        q += __shfl_xor_sync(0xffffffffu, q, o);
    }
    float mean = s * (1.0f / 256.0f);
    float var  = q * (1.0f / 256.0f) - mean * mean;
    float inv  = rsqrtf(var + 1e-5f);

    const float4* g4 = (const float4*)g;
    const float4* b4 = (const float4*)b;
    float4 ga = g4[lane], gb = g4[lane + 32];
    float4 ba = b4[lane], bb = b4[lane + 32];

    __half2 h0 = __floats2half2_rn((v0.x - mean) * inv * ga.x + ba.x,
                                   (v0.y - mean) * inv * ga.y + ba.y);
    __half2 h1 = __floats2half2_rn((v0.z - mean) * inv * ga.z + ba.z,
                                   (v0.w - mean) * inv * ga.w + ba.w);
    __half2 h2 = __floats2half2_rn((v1.x - mean) * inv * gb.x + bb.x,
                                   (v1.y - mean) * inv * gb.y + bb.y);
    __half2 h3 = __floats2half2_rn((v1.z - mean) * inv * gb.z + bb.z,
                                   (v1.w - mean) * inv * gb.w + bb.w);

    __half* orow = out + (size_t)row * DIM;
    uint2 p0; p0.x = *(uint32_t*)&h0; p0.y = *(uint32_t*)&h1;
    uint2 p1; p1.x = *(uint32_t*)&h2; p1.y = *(uint32_t*)&h3;
    *(uint2*)(orow + lane * 4)       = p0;
    *(uint2*)(orow + 128 + lane * 4) = p1;
}

// ===================== init: weight rounding + LN1, one launch ==============
__global__ void __launch_bounds__(256) init_kernel(
    const float* __restrict__ qkv_w, const float* __restrict__ proj_w,
    const float* __restrict__ ffn_w1, const float* __restrict__ ffn_w2,
    __half* __restrict__ wdst,
    const float* __restrict__ x, const float* __restrict__ ln1g,
    const float* __restrict__ ln1b, __half* __restrict__ xn)
{
    if (blockIdx.x < 768) {
        int i = blockIdx.x * 256 + threadIdx.x;      // float4 index
        const float* src;
        int local;
        if (i < 49152)       { src = qkv_w;  local = i;           }
        else if (i < 65536)  { src = proj_w; local = i - 49152;   }
        else if (i < 131072) { src = ffn_w1; local = i - 65536;   }
        else                 { src = ffn_w2; local = i - 131072;  }
        float4 v = ((const float4*)src)[local];
        __half2 lo = __floats2half2_rn(v.x, v.y);
        __half2 hi = __floats2half2_rn(v.z, v.w);
        uint2 o; o.x = *(uint32_t*)&lo; o.y = *(uint32_t*)&hi;
        ((uint2*)wdst)[i] = o;
    } else {
        int row = ((blockIdx.x - 768) * 256 + threadIdx.x) >> 5;
        ln_row(x, ln1g, ln1b, xn, row, threadIdx.x & 31);
    }
}

// ===================== LayerNorm (LN2) ======================================
__global__ void __launch_bounds__(256) ln_kernel(
    const float* __restrict__ x, const float* __restrict__ g,
    const float* __restrict__ b, __half* __restrict__ out)
{
    int row  = (blockIdx.x * blockDim.x + threadIdx.x) >> 5;
    ln_row(x, g, b, out, row, threadIdx.x & 31);
}

// ===================== Per-token head-mixing attention ======================
__global__ void __launch_bounds__(256) attn_kernel(
    const __half* __restrict__ qkv, __half* __restrict__ out)
{
    const int idx = blockIdx.x * 256 + threadIdx.x;  // (token, head)
    const int t = idx >> 3;
    const int h = idx & 7;
    const __half* base = qkv + (size_t)t * 768;

    float q[HD];
#pragma unroll
    for (int c4 = 0; c4 < 4; c4++) {
        uint4 qv = *(const uint4*)(base + h * HD + c4 * 8);
        const __half2* qh = (const __half2*)&qv;
#pragma unroll
        for (int j = 0; j < 4; j++) {
            float2 f = __half22float2(qh[j]);
            q[c4 * 8 + 2*j] = f.x; q[c4 * 8 + 2*j + 1] = f.y;
        }
    }

    const float scale = 0.17677669529663688f;   // 1/sqrt(32)
    float sc[HEADS];
    float mx = -1e30f;
#pragma unroll
    for (int g = 0; g < HEADS; g++) {
        float s = 0.0f;
#pragma unroll
        for (int c4 = 0; c4 < 4; c4++) {
            uint4 kv = *(const uint4*)(base + 256 + g * HD + c4 * 8);
            const __half2* kh = (const __half2*)&kv;
#pragma unroll
            for (int j = 0; j < 4; j++) {
                float2 f = __half22float2(kh[j]);
                s += q[c4 * 8 + 2*j] * f.x + q[c4 * 8 + 2*j + 1] * f.y;
            }
        }
        s *= scale;
        sc[g] = s;
        mx = fmaxf(mx, s);
    }
    float sum = 0.0f;
#pragma unroll
    for (int g = 0; g < HEADS; g++) {
        float e = __expf(sc[g] - mx);
        sc[g] = e;
        sum += e;
    }
    const float inv = 1.0f / sum;

    float acc[HD];
#pragma unroll
    for (int d0 = 0; d0 < HD; d0++) acc[d0] = 0.0f;
#pragma unroll
    for (int g = 0; g < HEADS; g++) {
        const float p = sc[g];
#pragma unroll
        for (int c4 = 0; c4 < 4; c4++) {
            uint4 vv = *(const uint4*)(base + 512 + g * HD + c4 * 8);
            const __half2* vh = (const __half2*)&vv;
#pragma unroll
            for (int j = 0; j < 4; j++) {
                float2 f = __half22float2(vh[j]);
                acc[c4 * 8 + 2*j]     += p * f.x;
                acc[c4 * 8 + 2*j + 1] += p * f.y;
            }
        }
    }

    __half* orow = out + (size_t)t * DIM + h * HD;
#pragma unroll
    for (int c4 = 0; c4 < 4; c4++) {
        __half2 o0 = __floats2half2_rn(acc[c4*8+0] * inv, acc[c4*8+1] * inv);
        __half2 o1 = __floats2half2_rn(acc[c4*8+2] * inv, acc[c4*8+3] * inv);
        __half2 o2 = __floats2half2_rn(acc[c4*8+4] * inv, acc[c4*8+5] * inv);
        __half2 o3 = __floats2half2_rn(acc[c4*8+6] * inv, acc[c4*8+7] * inv);
        uint4 p;
        p.x = *(uint32_t*)&o0; p.y = *(uint32_t*)&o1;
        p.z = *(uint32_t*)&o2; p.w = *(uint32_t*)&o3;
        *(uint4*)(orow + c4 * 8) = p;
    }
}

// ===================== Launch ===============================================
extern "C" void kernel_launch(void* const* d_in, const int* in_sizes, int n_in,
                              void* d_out, int out_size)
{
    const float* x      = (const float*)d_in[0];
    const float* ln1_g  = (const float*)d_in[1];
    const float* ln1_b  = (const float*)d_in[2];
    const float* qkv_w  = (const float*)d_in[3];
    const float* qkv_b  = (const float*)d_in[4];
    const float* proj_w = (const float*)d_in[5];
    const float* proj_b = (const float*)d_in[6];
    const float* ln2_g  = (const float*)d_in[7];
    const float* ln2_b  = (const float*)d_in[8];
    const float* ffn_w1 = (const float*)d_in[9];
    const float* ffn_b1 = (const float*)d_in[10];
    const float* ffn_w2 = (const float*)d_in[11];
    const float* ffn_b2 = (const float*)d_in[12];

    __half *xn, *qkv, *attn, *h, *w;
    float  *y;
    cudaGetSymbolAddress((void**)&xn,   g_xn);
    cudaGetSymbolAddress((void**)&qkv,  g_qkv);
    cudaGetSymbolAddress((void**)&attn, g_attn);
    cudaGetSymbolAddress((void**)&y,    g_y);
    cudaGetSymbolAddress((void**)&h,    g_h);
    cudaGetSymbolAddress((void**)&w,    g_w);
    float* out = (float*)d_out;

    cudaFuncSetAttribute(mma_gemm<0, __half>,
                         cudaFuncAttributeMaxDynamicSharedMemorySize, GEMM_SMEM);
    cudaFuncSetAttribute(mma_gemm<1, __half>,
                         cudaFuncAttributeMaxDynamicSharedMemorySize, GEMM_SMEM);
    cudaFuncSetAttribute(mma_gemm<2, float>,
                         cudaFuncAttributeMaxDynamicSharedMemorySize, GEMM_SMEM);

    const int MROWS = TOKENS / TILE;   // 512

    // 0+1) weight rounding + LN1 in one launch
    init_kernel<<<768 + TOKENS / 8, 256>>>(
        qkv_w, proj_w, ffn_w1, ffn_w2, w, x, ln1_g, ln1_b, xn);
    // 2) QKV = xn @ qkv_w^T + qkv_b          [65536, 768] half
    mma_gemm<0, __half><<<dim3(768 / TILE, MROWS), 128, GEMM_SMEM>>>(
        xn, w + W_QKV, qkv_b, nullptr, qkv, DIM, 3 * DIM);
    // 3) per-token head-mixing attention (half out)
    attn_kernel<<<TOKENS * 8 / 256, 256>>>(qkv, attn);
    // 4) y = x + attn @ proj_w^T + proj_b    [65536, 256] f32
    mma_gemm<2, float><<<dim3(DIM / TILE, MROWS), 128, GEMM_SMEM>>>(
        attn, w + W_PROJ, proj_b, x, y, DIM, DIM);
    // 5) LN2 (half out)
    ln_kernel<<<TOKENS / 8, 256>>>(y, ln2_g, ln2_b, xn);
    // 6) h = relu(xn @ ffn_w1^T + ffn_b1)    [65536, 1024] half
    mma_gemm<1, __half><<<dim3(FFNDIM / TILE, MROWS), 128, GEMM_SMEM>>>(
        xn, w + W_FFN1, ffn_b1, nullptr, h, DIM, FFNDIM);
    // 7) out = y + h @ ffn_w2^T + ffn_b2     [65536, 256] f32
    mma_gemm<2, float><<<dim3(DIM / TILE, MROWS), 128, GEMM_SMEM>>>(
        h, w + W_FFN2, ffn_b2, y, out, FFNDIM, DIM);
}